// round 6
// baseline (speedup 1.0000x reference)
#include <cuda_runtime.h>
#include <cstdint>

#define N_PRE    50000
#define VEC_DIM  300        // 75 float4
#define HIDDEN   128        // 32 float4
#define IN_SIZE  50000
#define OUT_U    107        // float4 units per token row (75 vec + 32 hidden)
#define N_TOKENS (64 * 200)
#define TOTAL_U  (N_TOKENS * OUT_U)      // 1,369,600 float4 units

#define NBLK   2675
#define NTHR   128
#define BATCH  4
// NBLK*NTHR*BATCH == TOTAL_U exactly (2675*128*4 = 1,369,600): no bounds checks.

// Flat unit-parallel kernel. Unit u -> token t = u/107, part p = u%107.
//   p <  75 : vector part  (copy vectors4[tok*75+p] if pre, else 0)
//   p >= 75 : hidden float4 j=p-75 covering rows h=4j..4j+3:
//             b4[j] (+ W[h, tok-N_PRE] gathers if oov)
// Each thread owns BATCH=4 units strided by grid size; all loads for the 4
// units are independent -> front-batched by ptxas -> high MLP.
__global__ __launch_bounds__(NTHR) void encoder_kernel(
    const int*    __restrict__ tokens,
    const float4* __restrict__ vectors4,
    const float*  __restrict__ W,        // [HIDDEN, IN_SIZE]
    const float4* __restrict__ b4,       // [32]
    float4*       __restrict__ out4)     // [TOTAL_U]
{
    const unsigned stride = NBLK * NTHR;               // 342400
    const unsigned u0 = blockIdx.x * NTHR + threadIdx.x;

    unsigned u[BATCH], t[BATCH], p[BATCH];
    int tok[BATCH];

    // phase 1: independent token loads (tokens is 50KB, L1/L2-hot)
    #pragma unroll
    for (int k = 0; k < BATCH; k++) {
        u[k] = u0 + k * stride;
        t[k] = u[k] / OUT_U;               // mul-shift by ptxas
        p[k] = u[k] - t[k] * OUT_U;
        tok[k] = __ldg(&tokens[t[k]]);
    }

    // phase 2: gather results (all loads across k independent)
    float4 r[BATCH];
    #pragma unroll
    for (int k = 0; k < BATCH; k++) {
        const bool pre = tok[k] < N_PRE;
        if (p[k] < 75) {
            if (pre) {
                r[k] = __ldg(&vectors4[(size_t)tok[k] * 75 + p[k]]);
            } else {
                r[k] = make_float4(0.f, 0.f, 0.f, 0.f);
            }
        } else {
            const unsigned j = p[k] - 75;          // hidden float4 index
            float4 bb = __ldg(&b4[j]);
            if (!pre) {
                const int c = tok[k] - N_PRE;
                const float* Wc = W + c + (size_t)(4 * j) * IN_SIZE;
                bb.x += __ldg(Wc);
                bb.y += __ldg(Wc + (size_t)IN_SIZE);
                bb.z += __ldg(Wc + (size_t)2 * IN_SIZE);
                bb.w += __ldg(Wc + (size_t)3 * IN_SIZE);
            }
            r[k] = bb;
        }
    }

    // phase 3: fully coalesced streaming stores
    #pragma unroll
    for (int k = 0; k < BATCH; k++) {
        __stcs(&out4[u[k]], r[k]);
    }
}

extern "C" void kernel_launch(void* const* d_in, const int* in_sizes, int n_in,
                              void* d_out, int out_size)
{
    const int*    tokens  = (const int*)   d_in[0];
    const float4* vectors = (const float4*)d_in[1];
    const float*  W       = (const float*) d_in[2];
    const float4* b       = (const float4*)d_in[3];
    float4*       out     = (float4*)      d_out;

    encoder_kernel<<<NBLK, NTHR>>>(tokens, vectors, W, b, out);
}